// round 17
// baseline (speedup 1.0000x reference)
#include <cuda_runtime.h>
#include <cstdint>

// CRF forward scan — TWO compile-time-specialized 64-thread engines per
// 128-thread block. Engine PAIR (warps 2P,2P+1 -> SMSPs 2P,2P+1) runs batch
// 2*blockIdx.x+PAIR with the exact R15 body: thread owns state tid64; packed
// f32x2 partials over own warp's v-half for columns tid64 (kept) and
// tid64^32 (published as one u64); ONE named barrier (immediate id) per step.
// Shift m = stale-by-1 alpha[1]. alpha base-2 scaled; ex2/lg2 approx PTX.
// feats/masks staged via per-engine cp.async 3-buffer pipeline.

#define TT 64
#define CHUNK 16
#define L2E 1.4426950408889634f
#define LN2 0.6931471805599453f
typedef unsigned long long u64;

__device__ float g_Wt[TT * TT];  // g_Wt[j*64+i] = exp(trans[i][j]-c_j)
__device__ float g_c2[TT];       // c_j * log2(e)

__device__ __forceinline__ void unpack2(u64 v, float& lo, float& hi) {
    asm("mov.b64 {%0, %1}, %2;" : "=f"(lo), "=f"(hi) : "l"(v));
}
__device__ __forceinline__ u64 ffma2(u64 a, u64 b, u64 c) {
    u64 d; asm("fma.rn.f32x2 %0, %1, %2, %3;" : "=l"(d) : "l"(a), "l"(b), "l"(c)); return d;
}
__device__ __forceinline__ u64 fadd2(u64 a, u64 b) {
    u64 d; asm("add.rn.f32x2 %0, %1, %2;" : "=l"(d) : "l"(a), "l"(b)); return d;
}
__device__ __forceinline__ float ex2f(float x) {
    float y; asm("ex2.approx.f32 %0, %1;" : "=f"(y) : "f"(x)); return y;
}
__device__ __forceinline__ float lg2f(float x) {
    float y; asm("lg2.approx.f32 %0, %1;" : "=f"(y) : "f"(x)); return y;
}
__device__ __forceinline__ uint32_t smem_u32(const void* p) {
    uint32_t a;
    asm("{ .reg .u64 t; cvta.to.shared.u64 t, %1; cvt.u32.u64 %0, t; }" : "=r"(a) : "l"(p));
    return a;
}

struct SmemEngine {
    alignas(16) float feat[3][CHUNK][TT];   // 12 KB staged feats
    float mask[3][CHUNK];
    alignas(16) float v[TT];                // single buffer (barrier-ordered)
    u64 part[2][TT];                        // packed partials, double buffered
    float mring[2];                         // stale alpha[1] ring
};

// ---------------------------------------------------------------------------
__global__ void crf_prep_kernel(const float* __restrict__ trans) {
    int j = threadIdx.x;
    float c = -3.402823466e+38f;
    #pragma unroll
    for (int i = 0; i < TT; i++) c = fmaxf(c, trans[i * TT + j]);
    g_c2[j] = c * L2E;
    #pragma unroll
    for (int i = 0; i < TT; i++) g_Wt[j * TT + i] = __expf(trans[i * TT + j] - c);
}

// ---------------------------------------------------------------------------
template <int PAIR>
__device__ __forceinline__ void engine(
    SmemEngine& S,
    const float* __restrict__ feats,
    const float* __restrict__ masks,
    float* __restrict__ out,
    int Sdim, int Bn)
{
    const int tid = threadIdx.x - 64 * PAIR;   // 0..63 (constant fold)
    const int w2  = tid >> 5;
    int b = blockIdx.x * 2 + PAIR;
    if (b >= Bn) b = Bn - 1;                   // duplicate batch: benign

    // Named barrier with IMMEDIATE id (1 or 2), 64 threads.
    auto barsync = [] {
        asm volatile("bar.sync %0, 64;" :: "n"(PAIR + 1) : "memory");
    };

    // W columns tid (own) and tid^32, rows [32*w2, 32*w2+32), pre-packed u64.
    u64 wA[16], wB[16];
    {
        const ulonglong2* pa =
            reinterpret_cast<const ulonglong2*>(&g_Wt[tid * TT + 32 * w2]);
        const ulonglong2* pb =
            reinterpret_cast<const ulonglong2*>(&g_Wt[(tid ^ 32) * TT + 32 * w2]);
        #pragma unroll
        for (int q = 0; q < 8; q++) {
            ulonglong2 ua = pa[q];
            wA[2 * q]     = ua.x;
            wA[2 * q + 1] = ua.y;
            ulonglong2 ub = pb[q];
            wB[2 * q]     = ub.x;
            wB[2 * q + 1] = ub.y;
        }
    }
    const float cj2 = g_c2[tid];

    const float* fbp = feats + (size_t)b * Sdim * TT;
    const float* mbp = masks + (size_t)b * Sdim;
    const uint32_t feat_s0 = smem_u32(&S.feat[0][0][0]);
    const uint32_t mask_s0 = smem_u32(&S.mask[0][0]);

    const int NC   = (Sdim + CHUNK - 1) / CHUNK;
    const int tail = Sdim - (NC - 1) * CHUNK;

    auto stage = [&](int c) {
        const int base = c * CHUNK;
        const int bufo = (c % 3) * CHUNK * TT;
        #pragma unroll
        for (int q = 0; q < 4; q++) {
            int g   = q * 64 + tid;        // 16B granule 0..255
            int row = g >> 4;
            int col = (g & 15) << 2;
            int gr  = base + row; if (gr >= Sdim) gr = Sdim - 1;
            const float* src = fbp + (size_t)gr * TT + col;
            uint32_t dst = feat_s0 + (uint32_t)(bufo + row * TT + col) * 4u;
            asm volatile("cp.async.cg.shared.global [%0], [%1], 16;" :: "r"(dst), "l"(src));
        }
        if (tid < CHUNK) {
            int gr = base + tid; if (gr >= Sdim) gr = Sdim - 1;
            const float* src = mbp + gr;
            uint32_t dst = mask_s0 + (uint32_t)((c % 3) * CHUNK + tid) * 4u;
            asm volatile("cp.async.ca.shared.global [%0], [%1], 4;" :: "r"(dst), "l"(src));
        }
    };

    stage(0);
    asm volatile("cp.async.commit_group;");
    if (NC > 1) stage(1);
    asm volatile("cp.async.commit_group;");
    asm volatile("cp.async.wait_group 1;");
    barsync();

    float alpha = S.feat[0][0][tid] * L2E;   // base-2 scaled alpha0

    if (tid == 1) S.mring[1] = alpha;        // slot 1 read at t=1
    barsync();
    float m = S.mring[1];

    auto step = [&](const float* fchunk, const float* mchunk, int r) {
        // Chain head: exp2 with stale shift; publish own v (constant addr).
        const float v = ex2f(alpha - m);
        S.v[tid] = v;

        // Publish alpha[1] for step t+1's shift.
        if (tid == 1) S.mring[(r & 1) ^ 1] = alpha;

        // Off-chain: staged feat/mask, pre-activation.
        const float ft  = fchunk[r * TT + tid];
        const float mk  = mchunk[r];
        const float pre = fmaf(ft, L2E, cj2 + m);

        __syncwarp();

        // Own-half matvec for columns tid and tid^32 (2 accs per column).
        const ulonglong2* vp =
            reinterpret_cast<const ulonglong2*>(&S.v[32 * w2]);
        u64 a0 = 0ull, a1 = 0ull, b0 = 0ull, b1 = 0ull;
        #pragma unroll
        for (int q = 0; q < 8; q++) {
            ulonglong2 u = vp[q];
            a0 = ffma2(u.x, wA[2 * q],     a0);
            a1 = ffma2(u.y, wA[2 * q + 1], a1);
            b0 = ffma2(u.x, wB[2 * q],     b0);
            b1 = ffma2(u.y, wB[2 * q + 1], b1);
        }
        const u64 sA = fadd2(a0, a1);       // own column, own half (packed)
        const u64 sB = fadd2(b0, b1);       // partner column, own half

        S.part[r & 1][tid ^ 32] = sB;       // publish packed partial

        barsync();                          // the ONLY barrier (named, imm id)

        // Tail: packed combine, horizontal add, log2, masked select.
        const u64 comb = fadd2(sA, S.part[r & 1][tid]);
        float lo, hi;
        unpack2(comb, lo, hi);
        const float P = lo + hi;
        const float na = pre + lg2f(P);
        alpha = (mk != 0.0f) ? na : alpha;
        m = S.mring[(r & 1) ^ 1];
    };

    for (int c = 0; c < NC; c++) {
        if (c > 0) asm volatile("cp.async.wait_group 1;");
        if (c + 2 < NC) stage(c + 2);
        asm volatile("cp.async.commit_group;");             // uniform count
        barsync();

        const float* fchunk = &S.feat[c % 3][0][0];
        const float* mchunk = &S.mask[c % 3][0];

        if (c + 1 < NC) {
            #pragma unroll
            for (int r = 0; r < CHUNK; r++) {
                if (r == 0 && c == 0) continue;   // skip t = 0 only
                step(fchunk, mchunk, r);
            }
        } else {
            for (int r = 0; r < tail; r++) {
                if (r == 0 && c == 0) continue;
                step(fchunk, mchunk, r);
            }
        }
    }

    out[(size_t)b * TT + tid] = alpha * LN2;
}

// ---------------------------------------------------------------------------
__global__ void __launch_bounds__(128) crf_scan_kernel(
    const float* __restrict__ feats,
    const float* __restrict__ masks,
    float* __restrict__ out,
    int Sdim, int Bn)
{
    __shared__ SmemEngine sm[2];   // ~27 KB

    if (threadIdx.x < 64) {
        engine<0>(sm[0], feats, masks, out, Sdim, Bn);
    } else {
        engine<1>(sm[1], feats, masks, out, Sdim, Bn);
    }
}

// ---------------------------------------------------------------------------
extern "C" void kernel_launch(void* const* d_in, const int* in_sizes, int n_in,
                              void* d_out, int out_size) {
    const float* feats = (const float*)d_in[0];
    const float* masks = (const float*)d_in[1];
    const float* trans = (const float*)d_in[2];
    float* out = (float*)d_out;

    const int Bn   = out_size / TT;
    const int Sdim = in_sizes[0] / (Bn * TT);

    crf_prep_kernel<<<1, TT>>>(trans);
    crf_scan_kernel<<<(Bn + 1) / 2, 128>>>(feats, masks, out, Sdim, Bn);
}